// round 16
// baseline (speedup 1.0000x reference)
#include <cuda_runtime.h>
#include <cuda_bf16.h>
#include <cstdint>
#include <cstddef>

// ---- problem constants ----
#define CH    256
#define CR    64
#define GRP   16
#define CPG   16
#define KK    49
#define HH    64
#define WW    64
#define NPIX  4096
#define BSZ   4

// ---- device scratch ----
__device__ unsigned short g_thi[BSZ * 32 * CR * 128];
__device__ unsigned short g_tlo[BSZ * 32 * CR * 128];
__device__ uint4 g_wfrag[GRP * 4 * 4 * 2 * 32];        // 256 KB

// ============================================================================
// PTX helpers
// ============================================================================
__device__ __forceinline__ uint32_t smem_u32(const void* p) {
    uint32_t a;
    asm("{ .reg .u64 t; cvta.to.shared.u64 t, %1; cvt.u32.u64 %0, t; }"
        : "=r"(a) : "l"(p));
    return a;
}
__device__ __forceinline__ void ldmatrix_x4_trans(uint32_t& b0, uint32_t& b1,
                                                  uint32_t& b2, uint32_t& b3, uint32_t addr) {
    asm volatile("ldmatrix.sync.aligned.m8n8.x4.trans.shared.b16 {%0,%1,%2,%3}, [%4];"
                 : "=r"(b0), "=r"(b1), "=r"(b2), "=r"(b3) : "r"(addr));
}
__device__ __forceinline__ void mma_bf16(float* c, const uint32_t* a,
                                         uint32_t b0, uint32_t b1) {
    asm volatile("mma.sync.aligned.m16n8k16.row.col.f32.bf16.bf16.f32 "
                 "{%0,%1,%2,%3}, {%4,%5,%6,%7}, {%8,%9}, {%0,%1,%2,%3};"
                 : "+f"(c[0]), "+f"(c[1]), "+f"(c[2]), "+f"(c[3])
                 : "r"(a[0]), "r"(a[1]), "r"(a[2]), "r"(a[3]), "r"(b0), "r"(b1));
}
#define PACK_F32X2(out, lo, hi) \
    asm("mov.b64 %0, {%1, %2};" : "=l"(out) : "f"(lo), "f"(hi))
#define FMA_F32X2(acc, w, x) \
    asm("fma.rn.f32x2 %0, %1, %2, %0;" : "+l"(acc) : "l"(w), "l"(x))
#define UNPACK_F32X2(lo, hi, in) \
    asm("mov.b64 {%0, %1}, %2;" : "=f"(lo), "=f"(hi) : "l"(in))

// ---- fused smem layout (float offsets). Region0: T hi/lo (phaseA) | xs (phaseB)
#define T_PITCH_B 272
#define T_LO_OFF  17408
#define XS_F      0
#define KS_F      9216
#define BS_F      15488
#define SMEM_FLOATS 15552
#define SMEM_BYTES  (SMEM_FLOATS * 4)

// reduce dynamic smem: 32 output-pairs x 256 k x u64 (w,w') = 64 KB
#define RED_SMEM_BYTES 65536

// ============================================================================
// Kernel 1: reduce (single x pass, output-pair packed f32x2) + wprep slices
// grid (80, 1, BSZ): x<64 -> reduce (64 px, all 64 outputs); x>=64 -> wprep.
// ============================================================================
extern __shared__ float sm[];

__global__ void __launch_bounds__(256) reduce_kernel(
        const float* __restrict__ x,
        const float* __restrict__ wr,
        const float* __restrict__ br,
        const float* __restrict__ wspan) {
    const int tid = threadIdx.x;

    if (blockIdx.x >= 64) {
        // ---- wprep: pack w_span into MMA A-fragment layout (64 slices) ----
        const int idx  = ((blockIdx.x - 64) * BSZ + blockIdx.z) * 256 + tid;
        const int lane = idx & 31;
        const int hl   = (idx >> 5) & 1;
        const int ks   = (idx >> 6) & 3;
        const int mt   = (idx >> 8) & 3;
        const int g    = idx >> 10;

        uint32_t r[4];
        #pragma unroll
        for (int q = 0; q < 4; ++q) {
            const int m = mt * 16 + (lane >> 2) + (q & 1) * 8;
            const int k = ks * 16 + (lane & 3) * 2 + (q >> 1) * 8;
            const float v0 = (m < KK) ? wspan[(size_t)(g * KK + m) * 64 + k]     : 0.f;
            const float v1 = (m < KK) ? wspan[(size_t)(g * KK + m) * 64 + k + 1] : 0.f;
            const __nv_bfloat16 h0 = __float2bfloat16(v0);
            const __nv_bfloat16 h1 = __float2bfloat16(v1);
            if (hl == 0) {
                r[q] = ((uint32_t)__bfloat16_as_ushort(h1) << 16) | __bfloat16_as_ushort(h0);
            } else {
                const __nv_bfloat16 l0 = __float2bfloat16(v0 - __bfloat162float(h0));
                const __nv_bfloat16 l1 = __float2bfloat16(v1 - __bfloat162float(h1));
                r[q] = ((uint32_t)__bfloat16_as_ushort(l1) << 16) | __bfloat16_as_ushort(l0);
            }
        }
        g_wfrag[idx] = make_uint4(r[0], r[1], r[2], r[3]);
        return;
    }

    // ---- reduce: t[b, o, px] for all 64 o, 64 px per block, x read once ----
    unsigned long long* ws2 = reinterpret_cast<unsigned long long*>(sm);

    // stage packed weight pairs: ws2[p*256 + k] = (wr[2p][k], wr[2p+1][k])
    for (int i = tid; i < 32 * 256; i += 256) {
        const int p = i >> 8, k = i & 255;
        unsigned long long wp;
        PACK_F32X2(wp, wr[(size_t)(2 * p) * CH + k], wr[(size_t)(2 * p + 1) * CH + k]);
        ws2[i] = wp;
    }
    __syncthreads();

    const int b   = blockIdx.z;
    const int q   = tid >> 6;            // 0..3: output-pair octet
    const int pxl = tid & 63;
    const int px  = blockIdx.x * 64 + pxl;
    const float* xb = x + (size_t)b * CH * NPIX + px;

    unsigned long long acc[8];           // (o_even, o_odd) accumulators
    #pragma unroll
    for (int i = 0; i < 8; ++i) acc[i] = 0ULL;

    const ulonglong2* wq = reinterpret_cast<const ulonglong2*>(ws2) + (size_t)q * 8 * 128;

    #pragma unroll 4
    for (int k2 = 0; k2 < 128; ++k2) {   // 2 channels per iter
        const float xv0 = xb[(size_t)(2 * k2 + 0) * NPIX];
        const float xv1 = xb[(size_t)(2 * k2 + 1) * NPIX];
        unsigned long long xx0, xx1;
        PACK_F32X2(xx0, xv0, xv0);
        PACK_F32X2(xx1, xv1, xv1);
        #pragma unroll
        for (int p8 = 0; p8 < 8; ++p8) {
            const ulonglong2 w2 = wq[p8 * 128 + k2];   // broadcast LDS.128
            FMA_F32X2(acc[p8], w2.x, xx0);
            FMA_F32X2(acc[p8], w2.y, xx1);
        }
    }

    const int tile = px >> 7;
    const int pc   = px & 127;
    #pragma unroll
    for (int p8 = 0; p8 < 8; ++p8) {
        const int o0 = (q * 8 + p8) * 2;
        float a0, a1;
        UNPACK_F32X2(a0, a1, acc[p8]);
        const float v0 = a0 + br[o0];
        const float v1 = a1 + br[o0 + 1];
        const __nv_bfloat16 h0 = __float2bfloat16(v0);
        const __nv_bfloat16 h1 = __float2bfloat16(v1);
        const __nv_bfloat16 l0 = __float2bfloat16(v0 - __bfloat162float(h0));
        const __nv_bfloat16 l1 = __float2bfloat16(v1 - __bfloat162float(h1));
        const size_t base = (((size_t)b * 32 + tile) * CR) * 128 + pc;
        g_thi[base + (size_t)(o0    ) * 128] = __bfloat16_as_ushort(h0);
        g_thi[base + (size_t)(o0 + 1) * 128] = __bfloat16_as_ushort(h1);
        g_tlo[base + (size_t)(o0    ) * 128] = __bfloat16_as_ushort(l0);
        g_tlo[base + (size_t)(o0 + 1) * 128] = __bfloat16_as_ushort(l1);
    }
}

// ============================================================================
// Kernel 2: fused span (mma.sync bf16 3-pass) + involution apply  [R15 frozen]
// ============================================================================
__global__ void __launch_bounds__(256, 3) fused_kernel(
        const float* __restrict__ x,
        const float* __restrict__ bspan,
        float* __restrict__ out) {
    const int tile = blockIdx.x;
    const int g    = blockIdx.y;
    const int b    = blockIdx.z;
    const int tid  = threadIdx.x;
    const int p0g  = tile * 128;
    const int y0   = tile * 2;

    const uint32_t smb = smem_u32(sm);
    float* xs  = sm + XS_F;
    float* ksp = sm + KS_F;
    float* bss = sm + BS_F;

    const int warp = tid >> 5, lane = tid & 31;
    const int mt = warp & 3;
    const int nh = warp >> 2;

    // ---- prefetch W fragments (overlap T staging) ----
    uint4 Whi[4], Wlo[4];
    {
        const uint4* wf = g_wfrag + (size_t)(g * 4 + mt) * 256 + lane;
        #pragma unroll
        for (int ks = 0; ks < 4; ++ks) {
            Whi[ks] = wf[ks * 64];
            Wlo[ks] = wf[ks * 64 + 32];
        }
    }

    // ---- stage T hi/lo tiles + bias ----
    {
        const uint4* sh = reinterpret_cast<const uint4*>(
            g_thi + (size_t)(b * 32 + tile) * CR * 128);
        const uint4* sl = reinterpret_cast<const uint4*>(
            g_tlo + (size_t)(b * 32 + tile) * CR * 128);
        char* smc = reinterpret_cast<char*>(sm);
        #pragma unroll
        for (int i = tid; i < 1024; i += 256) {
            const int off = (i >> 4) * T_PITCH_B + (i & 15) * 16;
            *reinterpret_cast<uint4*>(smc + off)            = sh[i];
            *reinterpret_cast<uint4*>(smc + T_LO_OFF + off) = sl[i];
        }
        if (tid < KK) bss[tid] = bspan[g * KK + tid];
    }
    __syncthreads();

    // ---- Phase A: tensor-core mini-GEMM ks[49][128] = W @ t ----
    {
        float acc[8][4];
        #pragma unroll
        for (int i = 0; i < 8; ++i)
            #pragma unroll
            for (int j = 0; j < 4; ++j) acc[i][j] = 0.f;

        const uint32_t thb = smb;
        const uint32_t tlb = smb + T_LO_OFF;
        #pragma unroll
        for (int ks = 0; ks < 4; ++ks) {
            const uint32_t* Ah = reinterpret_cast<const uint32_t*>(&Whi[ks]);
            const uint32_t* Al = reinterpret_cast<const uint32_t*>(&Wlo[ks]);
            #pragma unroll
            for (int np = 0; np < 4; ++np) {
                const uint32_t off =
                    (uint32_t)((ks * 16 + (lane & 15)) * T_PITCH_B +
                               (nh * 64 + np * 16 + (lane >> 4) * 8) * 2);
                uint32_t h0, h1, h2, h3, l0, l1, l2, l3;
                ldmatrix_x4_trans(h0, h1, h2, h3, thb + off);
                ldmatrix_x4_trans(l0, l1, l2, l3, tlb + off);
                mma_bf16(acc[np * 2 + 0], Ah, h0, h1);
                mma_bf16(acc[np * 2 + 0], Ah, l0, l1);
                mma_bf16(acc[np * 2 + 0], Al, h0, h1);
                mma_bf16(acc[np * 2 + 1], Ah, h2, h3);
                mma_bf16(acc[np * 2 + 1], Ah, l2, l3);
                mma_bf16(acc[np * 2 + 1], Al, h2, h3);
            }
        }

        const int r0 = mt * 16 + (lane >> 2);
        const int r1 = r0 + 8;
        const int cc = (lane & 3) * 2;
        #pragma unroll
        for (int nt = 0; nt < 8; ++nt) {
            const int n0 = nh * 64 + nt * 8 + cc;
            if (r0 < KK) {
                const float bias = bss[r0];
                float2 v; v.x = acc[nt][0] + bias; v.y = acc[nt][1] + bias;
                *reinterpret_cast<float2*>(ksp + r0 * 128 + n0) = v;
            }
            if (r1 < KK) {
                const float bias = bss[r1];
                float2 v; v.x = acc[nt][2] + bias; v.y = acc[nt][3] + bias;
                *reinterpret_cast<float2*>(ksp + r1 * 128 + n0) = v;
            }
        }
    }
    __syncthreads();

    // ---- load x halo: coalesced linear pattern + carry addressing ----
    {
        const float* xg = x + ((size_t)b * CH + g * CPG) * NPIX;
        int row = tid / 72;
        int xi  = tid - row * 72;
        #pragma unroll
        for (int j = 0; j < 36; ++j) {
            const int gy = y0 + (row & 7) - 3;
            const int gx = xi - 3;
            float v = 0.f;
            if ((unsigned)gy < HH && (unsigned)gx < WW)
                v = xg[(size_t)(row >> 3) * NPIX + gy * WW + gx];
            xs[tid + j * 256] = v;
            xi += 40; row += 3;
            if (xi >= 72) { xi -= 72; row += 1; }
        }
    }
    __syncthreads();

    // ---- Phase B: apply. 128 threads = (cq -> 4 ch) x (pg -> 4 px) ----
    if (tid < 128) {
        const int pg = tid & 31;
        const int cq = tid >> 5;
        const int yy = pg >> 4;
        const int xx = (pg & 15) * 4;
        const int c0 = cq * 4;

        float acc[4][4];
        #pragma unroll
        for (int i = 0; i < 4; ++i)
            #pragma unroll
            for (int j = 0; j < 4; ++j) acc[i][j] = 0.f;

        const float4* ks4 = reinterpret_cast<const float4*>(ksp);

        #pragma unroll
        for (int ti = 0; ti < 7; ++ti) {
            float kv[7][4];
            #pragma unroll
            for (int tj = 0; tj < 7; ++tj)
                *reinterpret_cast<float4*>(kv[tj]) = ks4[(ti * 7 + tj) * 32 + pg];

            #pragma unroll
            for (int half = 0; half < 2; ++half) {
                float w0[12], w1[12];
                const float* r0 = xs + (size_t)((c0 + half * 2 + 0) * 8 + yy + ti) * 72 + xx;
                const float* r1 = xs + (size_t)((c0 + half * 2 + 1) * 8 + yy + ti) * 72 + xx;
                *reinterpret_cast<float4*>(w0 + 0) = *reinterpret_cast<const float4*>(r0 + 0);
                *reinterpret_cast<float4*>(w0 + 4) = *reinterpret_cast<const float4*>(r0 + 4);
                *reinterpret_cast<float4*>(w0 + 8) = *reinterpret_cast<const float4*>(r0 + 8);
                *reinterpret_cast<float4*>(w1 + 0) = *reinterpret_cast<const float4*>(r1 + 0);
                *reinterpret_cast<float4*>(w1 + 4) = *reinterpret_cast<const float4*>(r1 + 4);
                *reinterpret_cast<float4*>(w1 + 8) = *reinterpret_cast<const float4*>(r1 + 8);
                float* a0 = acc[half * 2 + 0];
                float* a1 = acc[half * 2 + 1];
                #pragma unroll
                for (int tj = 0; tj < 7; ++tj) {
                    a0[0] += kv[tj][0] * w0[tj + 0];
                    a0[1] += kv[tj][1] * w0[tj + 1];
                    a0[2] += kv[tj][2] * w0[tj + 2];
                    a0[3] += kv[tj][3] * w0[tj + 3];
                    a1[0] += kv[tj][0] * w1[tj + 0];
                    a1[1] += kv[tj][1] * w1[tj + 1];
                    a1[2] += kv[tj][2] * w1[tj + 2];
                    a1[3] += kv[tj][3] * w1[tj + 3];
                }
            }
        }

        #pragma unroll
        for (int ci = 0; ci < 4; ++ci) {
            const int c = g * CPG + c0 + ci;
            float4 v;
            v.x = acc[ci][0]; v.y = acc[ci][1]; v.z = acc[ci][2]; v.w = acc[ci][3];
            *reinterpret_cast<float4*>(out + ((size_t)b * CH + c) * NPIX + p0g + pg * 4) = v;
        }
    }
}

// ============================================================================
extern "C" void kernel_launch(void* const* d_in, const int* in_sizes, int n_in,
                              void* d_out, int out_size) {
    const float* x   = (const float*)d_in[0];
    const float* wr  = (const float*)d_in[1];
    const float* br  = (const float*)d_in[2];
    const float* wsp = (const float*)d_in[3];
    const float* bsp = (const float*)d_in[4];
    float* out = (float*)d_out;

    cudaFuncSetAttribute(reduce_kernel,
                         cudaFuncAttributeMaxDynamicSharedMemorySize, RED_SMEM_BYTES);
    cudaFuncSetAttribute(fused_kernel,
                         cudaFuncAttributeMaxDynamicSharedMemorySize, SMEM_BYTES);

    reduce_kernel<<<dim3(80, 1, BSZ), 256, RED_SMEM_BYTES>>>(x, wr, br, wsp);
    fused_kernel<<<dim3(32, GRP, BSZ), 256, SMEM_BYTES>>>(x, bsp, out);
}

// round 17
// speedup vs baseline: 1.2816x; 1.2816x over previous
#include <cuda_runtime.h>
#include <cuda_bf16.h>
#include <cstdint>
#include <cstddef>

// ---- problem constants ----
#define CH    256
#define CR    64
#define GRP   16
#define CPG   16
#define KK    49
#define HH    64
#define WW    64
#define NPIX  4096
#define BSZ   4

// ---- device scratch ----
__device__ unsigned short g_thi[BSZ * 32 * CR * 128];
__device__ unsigned short g_tlo[BSZ * 32 * CR * 128];
__device__ uint4 g_wfrag[GRP * 4 * 4 * 2 * 32];        // wspan A-fragments, 256 KB

// ============================================================================
// PTX helpers
// ============================================================================
__device__ __forceinline__ uint32_t smem_u32(const void* p) {
    uint32_t a;
    asm("{ .reg .u64 t; cvta.to.shared.u64 t, %1; cvt.u32.u64 %0, t; }"
        : "=r"(a) : "l"(p));
    return a;
}
__device__ __forceinline__ void ldmatrix_x4(uint32_t& a0, uint32_t& a1,
                                            uint32_t& a2, uint32_t& a3, uint32_t addr) {
    asm volatile("ldmatrix.sync.aligned.m8n8.x4.shared.b16 {%0,%1,%2,%3}, [%4];"
                 : "=r"(a0), "=r"(a1), "=r"(a2), "=r"(a3) : "r"(addr));
}
__device__ __forceinline__ void ldmatrix_x4_trans(uint32_t& b0, uint32_t& b1,
                                                  uint32_t& b2, uint32_t& b3, uint32_t addr) {
    asm volatile("ldmatrix.sync.aligned.m8n8.x4.trans.shared.b16 {%0,%1,%2,%3}, [%4];"
                 : "=r"(b0), "=r"(b1), "=r"(b2), "=r"(b3) : "r"(addr));
}
__device__ __forceinline__ void mma_bf16(float* c, const uint32_t* a,
                                         uint32_t b0, uint32_t b1) {
    asm volatile("mma.sync.aligned.m16n8k16.row.col.f32.bf16.bf16.f32 "
                 "{%0,%1,%2,%3}, {%4,%5,%6,%7}, {%8,%9}, {%0,%1,%2,%3};"
                 : "+f"(c[0]), "+f"(c[1]), "+f"(c[2]), "+f"(c[3])
                 : "r"(a[0]), "r"(a[1]), "r"(a[2]), "r"(a[3]), "r"(b0), "r"(b1));
}
__device__ __forceinline__ uint32_t bf16pack(float a, float b) {
    const __nv_bfloat16 h0 = __float2bfloat16(a);
    const __nv_bfloat16 h1 = __float2bfloat16(b);
    return ((uint32_t)__bfloat16_as_ushort(h1) << 16) | __bfloat16_as_ushort(h0);
}

// ---- fused smem layout (float offsets) ----
#define T_PITCH_B 272
#define T_LO_OFF  17408
#define XS_F      0
#define KS_F      9216
#define BS_F      15488
#define SMEM_FLOATS 15552
#define SMEM_BYTES  (SMEM_FLOATS * 4)

// ---- mma-reduce smem layout (bytes) ----
// xhi[128 rows x 272B] | xlo | wrhi[64 x 272B] | wrlo
#define RX_HI   0
#define RX_LO   34816
#define RW_HI   69632
#define RW_LO   87040
#define RED_SMEM_BYTES 104448

extern __shared__ float sm[];

// ============================================================================
// Kernel 1: mma-reduce (y==0) + wspan fragment prep (y==1)
// grid (32, 2, BSZ), 256 threads.
// y==0: t[64][128] = Wr[64x256] @ x[256][128] per (tile,b) via bf16 3-pass MMA.
// ============================================================================
__global__ void __launch_bounds__(256) reduce_kernel(
        const float* __restrict__ x,
        const float* __restrict__ wr,
        const float* __restrict__ br,
        const float* __restrict__ wspan) {
    const int tid = threadIdx.x;

    if (blockIdx.y == 1) {
        // ---- wspan prep: 64 effective blocks of 256 threads ----
        const int blk = blockIdx.x * BSZ + blockIdx.z;     // 0..127
        if (blk >= 64) return;
        const int idx  = blk * 256 + tid;                  // 0..16383
        const int lane = idx & 31;
        const int hl   = (idx >> 5) & 1;
        const int ks   = (idx >> 6) & 3;
        const int mt   = (idx >> 8) & 3;
        const int g    = idx >> 10;
        uint32_t r[4];
        #pragma unroll
        for (int q = 0; q < 4; ++q) {
            const int m = mt * 16 + (lane >> 2) + (q & 1) * 8;
            const int k = ks * 16 + (lane & 3) * 2 + (q >> 1) * 8;
            const float v0 = (m < KK) ? wspan[(size_t)(g * KK + m) * 64 + k]     : 0.f;
            const float v1 = (m < KK) ? wspan[(size_t)(g * KK + m) * 64 + k + 1] : 0.f;
            if (hl == 0) {
                r[q] = bf16pack(v0, v1);
            } else {
                const __nv_bfloat16 h0 = __float2bfloat16(v0);
                const __nv_bfloat16 h1 = __float2bfloat16(v1);
                r[q] = bf16pack(v0 - __bfloat162float(h0), v1 - __bfloat162float(h1));
            }
        }
        g_wfrag[idx] = make_uint4(r[0], r[1], r[2], r[3]);
        return;
    }

    // ---- mma-reduce: block = (tile, b) ----
    const int tile = blockIdx.x;
    const int b    = blockIdx.z;
    const uint32_t smb = smem_u32(sm);
    char* smc = reinterpret_cast<char*>(sm);

    const int warp = tid >> 5, lane = tid & 31;
    const int mt = warp & 3;             // out-row tile (16 rows)
    const int nh = warp >> 2;            // pixel half (64 px)

    float acc[8][4];
    #pragma unroll
    for (int i = 0; i < 8; ++i)
        #pragma unroll
        for (int j = 0; j < 4; ++j) acc[i][j] = 0.f;

    #pragma unroll
    for (int chunk = 0; chunk < 2; ++chunk) {
        if (chunk) __syncthreads();      // protect smem reuse from prior MMA reads

        // stage x chunk [128 ch x 128 px] fp32 -> bf16 hi/lo (16 float4/thread)
        {
            const float4* xsrc = reinterpret_cast<const float4*>(
                x + ((size_t)b * CH + chunk * 128) * NPIX + tile * 128);
            #pragma unroll
            for (int j = 0; j < 16; ++j) {
                const int i = tid + j * 256;
                const int r = i >> 5, q = i & 31;    // row 0..127, colq 0..31
                const float4 v = xsrc[(size_t)r * (NPIX / 4) + q];
                const uint32_t h01 = bf16pack(v.x, v.y);
                const uint32_t h23 = bf16pack(v.z, v.w);
                const __nv_bfloat16 hx = __float2bfloat16(v.x);
                const __nv_bfloat16 hy = __float2bfloat16(v.y);
                const __nv_bfloat16 hz = __float2bfloat16(v.z);
                const __nv_bfloat16 hw = __float2bfloat16(v.w);
                const uint32_t l01 = bf16pack(v.x - __bfloat162float(hx),
                                              v.y - __bfloat162float(hy));
                const uint32_t l23 = bf16pack(v.z - __bfloat162float(hz),
                                              v.w - __bfloat162float(hw));
                const int off = r * T_PITCH_B + q * 8;
                *reinterpret_cast<uint2*>(smc + RX_HI + off) = make_uint2(h01, h23);
                *reinterpret_cast<uint2*>(smc + RX_LO + off) = make_uint2(l01, l23);
            }
        }
        // stage wr chunk [64 out x 128 ch] fp32 -> bf16 hi/lo (16 float2/thread)
        {
            #pragma unroll
            for (int j = 0; j < 16; ++j) {
                const int i = tid + j * 256;
                const int o = i >> 6, c2 = i & 63;   // out 0..63, chpair 0..63
                const float2 v = *reinterpret_cast<const float2*>(
                    wr + (size_t)o * CH + chunk * 128 + c2 * 2);
                const __nv_bfloat16 h0 = __float2bfloat16(v.x);
                const __nv_bfloat16 h1 = __float2bfloat16(v.y);
                const int off = o * T_PITCH_B + c2 * 4;
                *reinterpret_cast<uint32_t*>(smc + RW_HI + off) = bf16pack(v.x, v.y);
                *reinterpret_cast<uint32_t*>(smc + RW_LO + off) =
                    bf16pack(v.x - __bfloat162float(h0), v.y - __bfloat162float(h1));
            }
        }
        __syncthreads();

        // MMA: 8 k-steps of 16 channels
        #pragma unroll
        for (int kk = 0; kk < 8; ++kk) {
            uint32_t Ah[4], Al[4];
            const uint32_t aoff =
                (uint32_t)((mt * 16 + (lane & 15)) * T_PITCH_B +
                           (kk * 16 + (lane >> 4) * 8) * 2);
            ldmatrix_x4(Ah[0], Ah[1], Ah[2], Ah[3], smb + RW_HI + aoff);
            ldmatrix_x4(Al[0], Al[1], Al[2], Al[3], smb + RW_LO + aoff);
            #pragma unroll
            for (int np = 0; np < 4; ++np) {
                const uint32_t boff =
                    (uint32_t)((kk * 16 + (lane & 15)) * T_PITCH_B +
                               (nh * 64 + np * 16 + (lane >> 4) * 8) * 2);
                uint32_t h0, h1, h2, h3, l0, l1, l2, l3;
                ldmatrix_x4_trans(h0, h1, h2, h3, smb + RX_HI + boff);
                ldmatrix_x4_trans(l0, l1, l2, l3, smb + RX_LO + boff);
                mma_bf16(acc[np * 2 + 0], Ah, h0, h1);
                mma_bf16(acc[np * 2 + 0], Ah, l0, l1);
                mma_bf16(acc[np * 2 + 0], Al, h0, h1);
                mma_bf16(acc[np * 2 + 1], Ah, h2, h3);
                mma_bf16(acc[np * 2 + 1], Ah, l2, l3);
                mma_bf16(acc[np * 2 + 1], Al, h2, h3);
            }
        }
    }

    // epilogue: +bias, split hi/lo, store to g_thi/g_tlo [b][tile][o][px]
    {
        const int r0 = mt * 16 + (lane >> 2);
        const int r1 = r0 + 8;
        const int cc = (lane & 3) * 2;
        const float b0 = br[r0];
        const float b1 = br[r1];
        const size_t base = ((size_t)b * 32 + tile) * CR * 128;
        #pragma unroll
        for (int nt = 0; nt < 8; ++nt) {
            const int n0 = nh * 64 + nt * 8 + cc;
            {
                const float v0 = acc[nt][0] + b0, v1 = acc[nt][1] + b0;
                const __nv_bfloat16 h0 = __float2bfloat16(v0);
                const __nv_bfloat16 h1 = __float2bfloat16(v1);
                *reinterpret_cast<uint32_t*>(g_thi + base + (size_t)r0 * 128 + n0) =
                    bf16pack(v0, v1);
                *reinterpret_cast<uint32_t*>(g_tlo + base + (size_t)r0 * 128 + n0) =
                    bf16pack(v0 - __bfloat162float(h0), v1 - __bfloat162float(h1));
            }
            {
                const float v0 = acc[nt][2] + b1, v1 = acc[nt][3] + b1;
                const __nv_bfloat16 h0 = __float2bfloat16(v0);
                const __nv_bfloat16 h1 = __float2bfloat16(v1);
                *reinterpret_cast<uint32_t*>(g_thi + base + (size_t)r1 * 128 + n0) =
                    bf16pack(v0, v1);
                *reinterpret_cast<uint32_t*>(g_tlo + base + (size_t)r1 * 128 + n0) =
                    bf16pack(v0 - __bfloat162float(h0), v1 - __bfloat162float(h1));
            }
        }
    }
}

// ============================================================================
// Kernel 2: fused span (mma.sync bf16 3-pass) + involution apply  [frozen]
// ============================================================================
__global__ void __launch_bounds__(256, 3) fused_kernel(
        const float* __restrict__ x,
        const float* __restrict__ bspan,
        float* __restrict__ out) {
    const int tile = blockIdx.x;
    const int g    = blockIdx.y;
    const int b    = blockIdx.z;
    const int tid  = threadIdx.x;
    const int p0g  = tile * 128;
    const int y0   = tile * 2;

    const uint32_t smb = smem_u32(sm);
    float* xs  = sm + XS_F;
    float* ksp = sm + KS_F;
    float* bss = sm + BS_F;

    const int warp = tid >> 5, lane = tid & 31;
    const int mt = warp & 3;
    const int nh = warp >> 2;

    uint4 Whi[4], Wlo[4];
    {
        const uint4* wf = g_wfrag + (size_t)(g * 4 + mt) * 256 + lane;
        #pragma unroll
        for (int ks = 0; ks < 4; ++ks) {
            Whi[ks] = wf[ks * 64];
            Wlo[ks] = wf[ks * 64 + 32];
        }
    }

    {
        const uint4* sh = reinterpret_cast<const uint4*>(
            g_thi + (size_t)(b * 32 + tile) * CR * 128);
        const uint4* sl = reinterpret_cast<const uint4*>(
            g_tlo + (size_t)(b * 32 + tile) * CR * 128);
        char* smc = reinterpret_cast<char*>(sm);
        #pragma unroll
        for (int i = tid; i < 1024; i += 256) {
            const int off = (i >> 4) * T_PITCH_B + (i & 15) * 16;
            *reinterpret_cast<uint4*>(smc + off)            = sh[i];
            *reinterpret_cast<uint4*>(smc + T_LO_OFF + off) = sl[i];
        }
        if (tid < KK) bss[tid] = bspan[g * KK + tid];
    }
    __syncthreads();

    {
        float acc[8][4];
        #pragma unroll
        for (int i = 0; i < 8; ++i)
            #pragma unroll
            for (int j = 0; j < 4; ++j) acc[i][j] = 0.f;

        const uint32_t thb = smb;
        const uint32_t tlb = smb + T_LO_OFF;
        #pragma unroll
        for (int ks = 0; ks < 4; ++ks) {
            const uint32_t* Ah = reinterpret_cast<const uint32_t*>(&Whi[ks]);
            const uint32_t* Al = reinterpret_cast<const uint32_t*>(&Wlo[ks]);
            #pragma unroll
            for (int np = 0; np < 4; ++np) {
                const uint32_t off =
                    (uint32_t)((ks * 16 + (lane & 15)) * T_PITCH_B +
                               (nh * 64 + np * 16 + (lane >> 4) * 8) * 2);
                uint32_t h0, h1, h2, h3, l0, l1, l2, l3;
                ldmatrix_x4_trans(h0, h1, h2, h3, thb + off);
                ldmatrix_x4_trans(l0, l1, l2, l3, tlb + off);
                mma_bf16(acc[np * 2 + 0], Ah, h0, h1);
                mma_bf16(acc[np * 2 + 0], Ah, l0, l1);
                mma_bf16(acc[np * 2 + 0], Al, h0, h1);
                mma_bf16(acc[np * 2 + 1], Ah, h2, h3);
                mma_bf16(acc[np * 2 + 1], Ah, l2, l3);
                mma_bf16(acc[np * 2 + 1], Al, h2, h3);
            }
        }

        const int r0 = mt * 16 + (lane >> 2);
        const int r1 = r0 + 8;
        const int cc = (lane & 3) * 2;
        #pragma unroll
        for (int nt = 0; nt < 8; ++nt) {
            const int n0 = nh * 64 + nt * 8 + cc;
            if (r0 < KK) {
                const float bias = bss[r0];
                float2 v; v.x = acc[nt][0] + bias; v.y = acc[nt][1] + bias;
                *reinterpret_cast<float2*>(ksp + r0 * 128 + n0) = v;
            }
            if (r1 < KK) {
                const float bias = bss[r1];
                float2 v; v.x = acc[nt][2] + bias; v.y = acc[nt][3] + bias;
                *reinterpret_cast<float2*>(ksp + r1 * 128 + n0) = v;
            }
        }
    }
    __syncthreads();

    {
        const float* xg = x + ((size_t)b * CH + g * CPG) * NPIX;
        int row = tid / 72;
        int xi  = tid - row * 72;
        #pragma unroll
        for (int j = 0; j < 36; ++j) {
            const int gy = y0 + (row & 7) - 3;
            const int gx = xi - 3;
            float v = 0.f;
            if ((unsigned)gy < HH && (unsigned)gx < WW)
                v = xg[(size_t)(row >> 3) * NPIX + gy * WW + gx];
            xs[tid + j * 256] = v;
            xi += 40; row += 3;
            if (xi >= 72) { xi -= 72; row += 1; }
        }
    }
    __syncthreads();

    if (tid < 128) {
        const int pg = tid & 31;
        const int cq = tid >> 5;
        const int yy = pg >> 4;
        const int xx = (pg & 15) * 4;
        const int c0 = cq * 4;

        float acc[4][4];
        #pragma unroll
        for (int i = 0; i < 4; ++i)
            #pragma unroll
            for (int j = 0; j < 4; ++j) acc[i][j] = 0.f;

        const float4* ks4 = reinterpret_cast<const float4*>(ksp);

        #pragma unroll
        for (int ti = 0; ti < 7; ++ti) {
            float kv[7][4];
            #pragma unroll
            for (int tj = 0; tj < 7; ++tj)
                *reinterpret_cast<float4*>(kv[tj]) = ks4[(ti * 7 + tj) * 32 + pg];

            #pragma unroll
            for (int half = 0; half < 2; ++half) {
                float w0[12], w1[12];
                const float* r0 = xs + (size_t)((c0 + half * 2 + 0) * 8 + yy + ti) * 72 + xx;
                const float* r1 = xs + (size_t)((c0 + half * 2 + 1) * 8 + yy + ti) * 72 + xx;
                *reinterpret_cast<float4*>(w0 + 0) = *reinterpret_cast<const float4*>(r0 + 0);
                *reinterpret_cast<float4*>(w0 + 4) = *reinterpret_cast<const float4*>(r0 + 4);
                *reinterpret_cast<float4*>(w0 + 8) = *reinterpret_cast<const float4*>(r0 + 8);
                *reinterpret_cast<float4*>(w1 + 0) = *reinterpret_cast<const float4*>(r1 + 0);
                *reinterpret_cast<float4*>(w1 + 4) = *reinterpret_cast<const float4*>(r1 + 4);
                *reinterpret_cast<float4*>(w1 + 8) = *reinterpret_cast<const float4*>(r1 + 8);
                float* a0 = acc[half * 2 + 0];
                float* a1 = acc[half * 2 + 1];
                #pragma unroll
                for (int tj = 0; tj < 7; ++tj) {
                    a0[0] += kv[tj][0] * w0[tj + 0];
                    a0[1] += kv[tj][1] * w0[tj + 1];
                    a0[2] += kv[tj][2] * w0[tj + 2];
                    a0[3] += kv[tj][3] * w0[tj + 3];
                    a1[0] += kv[tj][0] * w1[tj + 0];
                    a1[1] += kv[tj][1] * w1[tj + 1];
                    a1[2] += kv[tj][2] * w1[tj + 2];
                    a1[3] += kv[tj][3] * w1[tj + 3];
                }
            }
        }

        #pragma unroll
        for (int ci = 0; ci < 4; ++ci) {
            const int c = g * CPG + c0 + ci;
            float4 v;
            v.x = acc[ci][0]; v.y = acc[ci][1]; v.z = acc[ci][2]; v.w = acc[ci][3];
            *reinterpret_cast<float4*>(out + ((size_t)b * CH + c) * NPIX + p0g + pg * 4) = v;
        }
    }
}

// ============================================================================
extern "C" void kernel_launch(void* const* d_in, const int* in_sizes, int n_in,
                              void* d_out, int out_size) {
    const float* x   = (const float*)d_in[0];
    const float* wr  = (const float*)d_in[1];
    const float* br  = (const float*)d_in[2];
    const float* wsp = (const float*)d_in[3];
    const float* bsp = (const float*)d_in[4];
    float* out = (float*)d_out;

    cudaFuncSetAttribute(reduce_kernel,
                         cudaFuncAttributeMaxDynamicSharedMemorySize, RED_SMEM_BYTES);
    cudaFuncSetAttribute(fused_kernel,
                         cudaFuncAttributeMaxDynamicSharedMemorySize, SMEM_BYTES);

    reduce_kernel<<<dim3(32, 2, BSZ), 256, RED_SMEM_BYTES>>>(x, wr, br, wsp);
    fused_kernel<<<dim3(32, GRP, BSZ), 256, SMEM_BYTES>>>(x, bsp, out);
}